// round 2
// baseline (speedup 1.0000x reference)
#include <cuda_runtime.h>
#include <cuda_bf16.h>

// ---------------------------------------------------------------------------
// AttentionLayer: B=2, S1=S2=2048, D=1024, H=16, dh=64
// out layout: [ output (2*2048*1024) | attn_weights (2*16*2048*2048) ] fp32
// ---------------------------------------------------------------------------

#define BATCH 2
#define SEQ   2048
#define DEMB  1024
#define NHEAD 16
#define DHEAD 64

#define QKV_ELEMS (BATCH * SEQ * DEMB)          // 4,194,304
#define ATTN_OFF  ((size_t)BATCH * SEQ * DEMB)  // start of attn_weights in d_out

// Scratch (allocation-free rule: __device__ globals)
__device__ float g_Q[QKV_ELEMS];
__device__ float g_K[QKV_ELEMS];
__device__ float g_V[QKV_ELEMS];
__device__ float g_AO[QKV_ELEMS];

// ---------------------------------------------------------------------------
// Generic fp32 tiled GEMM.
//   TRANSB=true : C[m,n] = sum_k A[m,k] * B[n,k]   (B row-major [N,K], weights / K^T)
//   TRANSB=false: C[m,n] = sum_k A[m,k] * B[k,n]   (B row-major [K,N])
// Per-z (batch*head) base offsets: X += bidx*xOffB + h*xOffH, z = blockIdx.z.
// Requires: M%BM==0, N%BN==0, K%BK==0, BK%4==0, 4-float-aligned bases/lds.
// blockDim.x == (BM/TM)*(BN/TN) == 256.
// ---------------------------------------------------------------------------
template <int BM, int BN, int BK, int TM, int TN, bool TRANSB>
__global__ void gemm_tiled(const float* __restrict__ A,
                           const float* __restrict__ B,
                           const float* __restrict__ bias,
                           float* __restrict__ C,
                           int K, int lda, int ldb, int ldc,
                           size_t aOffB, size_t aOffH,
                           size_t bOffB, size_t bOffH,
                           size_t cOffB, size_t cOffH,
                           float scale)
{
    const int z    = blockIdx.z;
    const int bidx = z >> 4;       // z / NHEAD
    const int h    = z & 15;       // z % NHEAD
    A += (size_t)bidx * aOffB + (size_t)h * aOffH;
    B += (size_t)bidx * bOffB + (size_t)h * bOffH;
    C += (size_t)bidx * cOffB + (size_t)h * cOffH;

    const int tid = threadIdx.x;
    const int m0  = blockIdx.y * BM;
    const int n0  = blockIdx.x * BN;

    __shared__ float As[BK][BM];
    __shared__ float Bs[BK][BN];

    constexpr int NTX = BN / TN;           // threads along n
    const int tx = tid % NTX;
    const int ty = tid / NTX;

    float acc[TM][TN];
#pragma unroll
    for (int i = 0; i < TM; i++)
#pragma unroll
        for (int j = 0; j < TN; j++) acc[i][j] = 0.f;

    constexpr int A_LD_CNT = BM * BK / 4;  // float4 loads for A tile
    constexpr int B_LD_CNT = BN * BK / 4;  // float4 loads for B tile

    for (int k0 = 0; k0 < K; k0 += BK) {
        // --- load A tile -> As[k][m] (transposed) ---
        if (A_LD_CNT >= 256 || tid < A_LD_CNT) {
            const int r  = tid / (BK / 4);
            const int c4 = (tid % (BK / 4)) * 4;
            float4 v = *reinterpret_cast<const float4*>(&A[(size_t)(m0 + r) * lda + k0 + c4]);
            As[c4 + 0][r] = v.x;
            As[c4 + 1][r] = v.y;
            As[c4 + 2][r] = v.z;
            As[c4 + 3][r] = v.w;
        }
        // --- load B tile -> Bs[k][n] ---
        if (TRANSB) {
            if (B_LD_CNT >= 256 || tid < B_LD_CNT) {
                const int n  = tid / (BK / 4);
                const int c4 = (tid % (BK / 4)) * 4;
                float4 v = *reinterpret_cast<const float4*>(&B[(size_t)(n0 + n) * ldb + k0 + c4]);
                Bs[c4 + 0][n] = v.x;
                Bs[c4 + 1][n] = v.y;
                Bs[c4 + 2][n] = v.z;
                Bs[c4 + 3][n] = v.w;
            }
        } else {
            if (B_LD_CNT >= 256 || tid < B_LD_CNT) {
                const int k  = tid / (BN / 4);
                const int n4 = (tid % (BN / 4)) * 4;
                float4 v = *reinterpret_cast<const float4*>(&B[(size_t)(k0 + k) * ldb + n0 + n4]);
                *reinterpret_cast<float4*>(&Bs[k][n4]) = v;
            }
        }
        __syncthreads();

#pragma unroll
        for (int kk = 0; kk < BK; kk++) {
            float a[TM], b[TN];
#pragma unroll
            for (int i = 0; i < TM; i++) a[i] = As[kk][ty * TM + i];
#pragma unroll
            for (int j = 0; j < TN; j++) b[j] = Bs[kk][tx * TN + j];
#pragma unroll
            for (int i = 0; i < TM; i++)
#pragma unroll
                for (int j = 0; j < TN; j++) acc[i][j] += a[i] * b[j];
        }
        __syncthreads();
    }

    // --- epilogue ---
#pragma unroll
    for (int i = 0; i < TM; i++) {
        const size_t row = (size_t)(m0 + ty * TM + i) * ldc;
#pragma unroll
        for (int j = 0; j < TN; j++) {
            const int n = n0 + tx * TN + j;
            float v = acc[i][j] * scale;
            if (bias) v += bias[n];
            C[row + n] = v;
        }
    }
}

// ---------------------------------------------------------------------------
// In-place row softmax: one block per row of 2048 floats, 256 threads x 8.
// ---------------------------------------------------------------------------
__global__ void softmax_rows(float* __restrict__ P)
{
    const size_t base = (size_t)blockIdx.x * 2048;
    float* p = P + base;
    const int tid = threadIdx.x;

    float v[8];
    float m = -1e30f;
#pragma unroll
    for (int i = 0; i < 8; i++) {
        v[i] = p[tid + i * 256];
        m = fmaxf(m, v[i]);
    }
#pragma unroll
    for (int o = 16; o > 0; o >>= 1) m = fmaxf(m, __shfl_xor_sync(0xffffffffu, m, o));

    __shared__ float redM[8];
    __shared__ float redS[8];
    if ((tid & 31) == 0) redM[tid >> 5] = m;
    __syncthreads();
    float mAll = redM[0];
#pragma unroll
    for (int w = 1; w < 8; w++) mAll = fmaxf(mAll, redM[w]);

    float s = 0.f;
#pragma unroll
    for (int i = 0; i < 8; i++) {
        v[i] = __expf(v[i] - mAll);
        s += v[i];
    }
#pragma unroll
    for (int o = 16; o > 0; o >>= 1) s += __shfl_xor_sync(0xffffffffu, s, o);
    if ((tid & 31) == 0) redS[tid >> 5] = s;
    __syncthreads();
    float sAll = 0.f;
#pragma unroll
    for (int w = 0; w < 8; w++) sAll += redS[w];

    const float inv = 1.f / sAll;
#pragma unroll
    for (int i = 0; i < 8; i++) p[tid + i * 256] = v[i] * inv;
}

// ---------------------------------------------------------------------------

extern "C" void kernel_launch(void* const* d_in, const int* in_sizes, int n_in,
                              void* d_out, int out_size)
{
    const float* x1 = (const float*)d_in[0];
    const float* x2 = (const float*)d_in[1];
    const float* Wq = (const float*)d_in[2];
    const float* bq = (const float*)d_in[3];
    const float* Wk = (const float*)d_in[4];
    const float* bk = (const float*)d_in[5];
    const float* Wv = (const float*)d_in[6];
    const float* bv = (const float*)d_in[7];
    const float* Wo = (const float*)d_in[8];
    const float* bo = (const float*)d_in[9];
    float* out = (float*)d_out;

    // Resolve scratch symbols once (fixed symbols -> deterministic result;
    // avoids repeated runtime-API calls on the capture path).
    static float *Q = nullptr, *K = nullptr, *V = nullptr, *AO = nullptr;
    if (Q == nullptr) {
        cudaGetSymbolAddress((void**)&Q,  g_Q);
        cudaGetSymbolAddress((void**)&K,  g_K);
        cudaGetSymbolAddress((void**)&V,  g_V);
        cudaGetSymbolAddress((void**)&AO, g_AO);
    }

    const int M = BATCH * SEQ;            // 4096
    const size_t SD = (size_t)SEQ * DEMB; // per-batch stride in Q/K/V  (2,097,152)
    const size_t SS = (size_t)SEQ * SEQ;  // per-head attn stride       (4,194,304)
    float* P = out + ATTN_OFF;

    // 1) Q/K/V projections: [4096,1024] = X @ W^T + b
    {
        dim3 grid(DEMB / 128, M / 128, 1);
        gemm_tiled<128,128,8,8,8,true><<<grid,256>>>(x1, Wq, bq, Q,
            DEMB, DEMB, DEMB, DEMB, 0,0, 0,0, 0,0, 1.f);
        gemm_tiled<128,128,8,8,8,true><<<grid,256>>>(x2, Wk, bk, K,
            DEMB, DEMB, DEMB, DEMB, 0,0, 0,0, 0,0, 1.f);
        gemm_tiled<128,128,8,8,8,true><<<grid,256>>>(x2, Wv, bv, V,
            DEMB, DEMB, DEMB, DEMB, 0,0, 0,0, 0,0, 1.f);
    }

    // 2) scores = Q K^T / 8, per (b,h), written directly into attn region
    {
        dim3 grid(SEQ / 128, SEQ / 128, BATCH * NHEAD);
        gemm_tiled<128,128,8,8,8,true><<<grid,256>>>(Q, K, nullptr, P,
            DHEAD, DEMB, DEMB, SEQ,
            SD, (size_t)DHEAD,          // A offsets (b, h)
            SD, (size_t)DHEAD,          // B offsets
            (size_t)NHEAD * SS, SS,     // C offsets
            0.125f);
    }

    // 3) softmax rows (in place on d_out attn region)
    softmax_rows<<<BATCH * NHEAD * SEQ, 256>>>(P);

    // 4) attn_out = P @ V  (per (b,h): [2048,2048] @ [2048,64])
    {
        dim3 grid(DHEAD / 64, SEQ / 128, BATCH * NHEAD);
        gemm_tiled<128,64,8,8,4,false><<<grid,256>>>(P, V, nullptr, AO,
            SEQ, SEQ, DEMB, DEMB,
            (size_t)NHEAD * SS, SS,     // A offsets
            SD, (size_t)DHEAD,          // B offsets
            SD, (size_t)DHEAD,          // C offsets
            1.f);
    }

    // 5) output = AO @ Wo^T + bo
    {
        dim3 grid(DEMB / 128, M / 128, 1);
        gemm_tiled<128,128,8,8,8,true><<<grid,256>>>(AO, Wo, bo, out,
            DEMB, DEMB, DEMB, DEMB, 0,0, 0,0, 0,0, 1.f);
    }
}

// round 7
// speedup vs baseline: 2.2072x; 2.2072x over previous
#include <cuda_runtime.h>
#include <cuda_fp16.h>
#include <cstdint>

// ---------------------------------------------------------------------------
// AttentionLayer: B=2, S1=S2=2048, D=1024, H=16, dh=64
// out layout: [ output (2*2048*1024) | attn_weights (2*16*2048*2048) ] fp32
// GEMMs via mma.sync m16n8k16 (f16 in, f32 acc) with fp16 hi/lo split
// (3 accumulating passes) for ~fp32 accuracy. Baseline PTX only (no tcgen05).
// ---------------------------------------------------------------------------

#define BATCH 2
#define SEQ   2048
#define DEMB  1024
#define NHEAD 16
#define DHEAD 64

#define QKV_ELEMS (BATCH * SEQ * DEMB)          // 4,194,304
#define ATTN_OFF  ((size_t)BATCH * SEQ * DEMB)

// fp32 scratch
__device__ float g_Q [QKV_ELEMS];
__device__ float g_K [QKV_ELEMS];
__device__ float g_Vt[QKV_ELEMS];   // V transposed: [(b*1024 + h*64 + d)][s]
__device__ float g_AO[QKV_ELEMS];

// ---------------------------------------------------------------------------
// helpers
// ---------------------------------------------------------------------------
__device__ __forceinline__ void cpasync16(void* dst_smem, const void* src_gmem) {
    uint32_t d = (uint32_t)__cvta_generic_to_shared(dst_smem);
    asm volatile("cp.async.cg.shared.global [%0], [%1], 16;\n" :: "r"(d), "l"(src_gmem));
}
#define CP_COMMIT()  asm volatile("cp.async.commit_group;\n" ::: "memory")
#define CP_WAIT(n)   asm volatile("cp.async.wait_group %0;\n" :: "n"(n) : "memory")

// fp32 pair -> fp16 hi + fp16 lo (residual), packed b32
__device__ __forceinline__ void cvt2(float2 f, uint32_t& hi, uint32_t& lo) {
    __half2 h = __floats2half2_rn(f.x, f.y);
    float2 hf = __half22float2(h);
    __half2 l = __floats2half2_rn(f.x - hf.x, f.y - hf.y);
    hi = *reinterpret_cast<uint32_t*>(&h);
    lo = *reinterpret_cast<uint32_t*>(&l);
}

__device__ __forceinline__ void mma16816(float* c, const uint32_t* a, const uint32_t* b) {
    asm volatile(
        "mma.sync.aligned.m16n8k16.row.col.f32.f16.f16.f32 "
        "{%0,%1,%2,%3}, {%4,%5,%6,%7}, {%8,%9}, {%0,%1,%2,%3};\n"
        : "+f"(c[0]), "+f"(c[1]), "+f"(c[2]), "+f"(c[3])
        : "r"(a[0]), "r"(a[1]), "r"(a[2]), "r"(a[3]), "r"(b[0]), "r"(b[1]));
}

// ---------------------------------------------------------------------------
// mma.sync GEMM: C[m,n] = scale * sum_k A[m,k]*B[n,k] (+ bias[n])
// A row-major [M,K] (lda), B row-major [N,K] (ldb). BM=128, BN in {128,64}.
// 256 threads = 8 warps (2 x 4), warp tile 64 x (BN/4).
// Double-buffered cp.async fp32 tiles, k-step = 16 fp32.
// TRANS: epilogue writes transposed into g_Vt layout [(b*1024+n)][s].
// ---------------------------------------------------------------------------
template <int BN, bool TRANS>
__global__ void __launch_bounds__(256)
gemm_mma(const float* __restrict__ A, const float* __restrict__ B,
         const float* __restrict__ bias, float* __restrict__ C,
         int K, int lda, int ldb, int ldc,
         size_t aOffB, size_t aOffH,
         size_t bOffB, size_t bOffH,
         size_t cOffB, size_t cOffH,
         float scale)
{
    constexpr int NT = BN / 32;            // n-tiles per warp (8-wide each)
    __shared__ float sA[2][128][20];
    __shared__ float sB[2][BN][20];

    const int tid  = threadIdx.x;
    const int wid  = tid >> 5;
    const int lane = tid & 31;
    const int grp  = lane >> 2;            // 0..7
    const int qid  = lane & 3;             // 0..3
    const int wm   = (wid >> 2) * 64;      // warp row base within BM
    const int wn   = (wid & 3) * (BN / 4); // warp col base within BN

    const int z    = blockIdx.z;
    const int bidx = z >> 4;
    const int h    = z & 15;
    A += (size_t)bidx * aOffB + (size_t)h * aOffH;
    B += (size_t)bidx * bOffB + (size_t)h * bOffH;
    float* Cb = C + (size_t)bidx * cOffB + (size_t)h * cOffH;

    const int m0 = blockIdx.y * 128;
    const int n0 = blockIdx.x * BN;
    const float* Ab = A + (size_t)m0 * lda;
    const float* Bb = B + (size_t)n0 * ldb;

    float acc[4][NT][4];
#pragma unroll
    for (int mt = 0; mt < 4; mt++)
#pragma unroll
        for (int nt = 0; nt < NT; nt++)
#pragma unroll
            for (int i = 0; i < 4; i++) acc[mt][nt][i] = 0.f;

    const int NKB = K >> 4;

    // stage loader: 16 fp32 per row starting at k0
    auto load_stage = [&](int st, int k0) {
#pragma unroll 2
        for (int i = tid; i < 128 * 4; i += 256) {
            const int r = i >> 2, sgm = i & 3;
            cpasync16(&sA[st][r][sgm * 4], Ab + (size_t)r * lda + k0 + sgm * 4);
        }
#pragma unroll 1
        for (int i = tid; i < BN * 4; i += 256) {
            const int r = i >> 2, sgm = i & 3;
            cpasync16(&sB[st][r][sgm * 4], Bb + (size_t)r * ldb + k0 + sgm * 4);
        }
    };

    load_stage(0, 0);
    CP_COMMIT();

    for (int kb = 0; kb < NKB; kb++) {
        if (kb + 1 < NKB) {
            load_stage((kb + 1) & 1, (kb + 1) << 4);
            CP_COMMIT();
            CP_WAIT(1);
        } else {
            CP_WAIT(0);
        }
        __syncthreads();

        const int st = kb & 1;

        // A fragments (4 m-tiles)
        uint32_t aHi[4][4], aLo[4][4];
#pragma unroll
        for (int mt = 0; mt < 4; mt++) {
            const int r0 = wm + mt * 16 + grp;
            float2 f00 = *reinterpret_cast<const float2*>(&sA[st][r0    ][qid * 2    ]);
            float2 f10 = *reinterpret_cast<const float2*>(&sA[st][r0 + 8][qid * 2    ]);
            float2 f01 = *reinterpret_cast<const float2*>(&sA[st][r0    ][qid * 2 + 8]);
            float2 f11 = *reinterpret_cast<const float2*>(&sA[st][r0 + 8][qid * 2 + 8]);
            cvt2(f00, aHi[mt][0], aLo[mt][0]);
            cvt2(f10, aHi[mt][1], aLo[mt][1]);
            cvt2(f01, aHi[mt][2], aLo[mt][2]);
            cvt2(f11, aHi[mt][3], aLo[mt][3]);
        }
        // B fragments (NT n-tiles)
        uint32_t bHi[NT][2], bLo[NT][2];
#pragma unroll
        for (int nt = 0; nt < NT; nt++) {
            const int c0 = wn + nt * 8 + grp;
            float2 g0 = *reinterpret_cast<const float2*>(&sB[st][c0][qid * 2    ]);
            float2 g1 = *reinterpret_cast<const float2*>(&sB[st][c0][qid * 2 + 8]);
            cvt2(g0, bHi[nt][0], bLo[nt][0]);
            cvt2(g1, bHi[nt][1], bLo[nt][1]);
        }
        // 3-pass split MMA
#pragma unroll
        for (int mt = 0; mt < 4; mt++)
#pragma unroll
            for (int nt = 0; nt < NT; nt++) {
                mma16816(acc[mt][nt], aHi[mt], bHi[nt]);
                mma16816(acc[mt][nt], aHi[mt], bLo[nt]);
                mma16816(acc[mt][nt], aLo[mt], bHi[nt]);
            }
        __syncthreads();
    }

    // epilogue
#pragma unroll
    for (int mt = 0; mt < 4; mt++) {
#pragma unroll
        for (int nt = 0; nt < NT; nt++) {
            const float* cc = acc[mt][nt];
            const int row = m0 + wm + mt * 16 + grp;
            const int col = n0 + wn + nt * 8 + qid * 2;
            if (!TRANS) {
                float b0 = bias ? bias[col]     : 0.f;
                float b1 = bias ? bias[col + 1] : 0.f;
                float2 v0 = { cc[0] * scale + b0, cc[1] * scale + b1 };
                float2 v1 = { cc[2] * scale + b0, cc[3] * scale + b1 };
                *reinterpret_cast<float2*>(&Cb[(size_t)row * ldc + col]) = v0;
                *reinterpret_cast<float2*>(&Cb[(size_t)(row + 8) * ldc + col]) = v1;
            } else {
                // write transposed into g_Vt[(b*1024 + col)][s]
                const int b2 = row >> 11;
                const int s  = row & 2047;
                const float b0 = bias[col], b1 = bias[col + 1];
                C[((size_t)(b2 * 1024 + col    )) * 2048 + s]     = cc[0] + b0;
                C[((size_t)(b2 * 1024 + col + 1)) * 2048 + s]     = cc[1] + b1;
                C[((size_t)(b2 * 1024 + col    )) * 2048 + s + 8] = cc[2] + b0;
                C[((size_t)(b2 * 1024 + col + 1)) * 2048 + s + 8] = cc[3] + b1;
            }
        }
    }
}

// ---------------------------------------------------------------------------
// In-place row softmax: one block per row of 2048 floats, 256 threads x 8.
// ---------------------------------------------------------------------------
__global__ void softmax_rows(float* __restrict__ P)
{
    const size_t base = (size_t)blockIdx.x * 2048;
    float* p = P + base;
    const int tid = threadIdx.x;

    float v[8];
    float m = -1e30f;
#pragma unroll
    for (int i = 0; i < 8; i++) {
        v[i] = p[tid + i * 256];
        m = fmaxf(m, v[i]);
    }
#pragma unroll
    for (int o = 16; o > 0; o >>= 1) m = fmaxf(m, __shfl_xor_sync(0xffffffffu, m, o));

    __shared__ float redM[8];
    __shared__ float redS[8];
    if ((tid & 31) == 0) redM[tid >> 5] = m;
    __syncthreads();
    float mAll = redM[0];
#pragma unroll
    for (int w = 1; w < 8; w++) mAll = fmaxf(mAll, redM[w]);

    float s = 0.f;
#pragma unroll
    for (int i = 0; i < 8; i++) {
        v[i] = __expf(v[i] - mAll);
        s += v[i];
    }
#pragma unroll
    for (int o = 16; o > 0; o >>= 1) s += __shfl_xor_sync(0xffffffffu, s, o);
    if ((tid & 31) == 0) redS[tid >> 5] = s;
    __syncthreads();
    float sAll = 0.f;
#pragma unroll
    for (int w = 0; w < 8; w++) sAll += redS[w];

    const float inv = 1.f / sAll;
#pragma unroll
    for (int i = 0; i < 8; i++) p[tid + i * 256] = v[i] * inv;
}

// ---------------------------------------------------------------------------

extern "C" void kernel_launch(void* const* d_in, const int* in_sizes, int n_in,
                              void* d_out, int out_size)
{
    const float* x1 = (const float*)d_in[0];
    const float* x2 = (const float*)d_in[1];
    const float* Wq = (const float*)d_in[2];
    const float* bq = (const float*)d_in[3];
    const float* Wk = (const float*)d_in[4];
    const float* bk = (const float*)d_in[5];
    const float* Wv = (const float*)d_in[6];
    const float* bv = (const float*)d_in[7];
    const float* Wo = (const float*)d_in[8];
    const float* bo = (const float*)d_in[9];
    float* out = (float*)d_out;

    static float *Q = nullptr, *K = nullptr, *Vt = nullptr, *AO = nullptr;
    if (Q == nullptr) {
        cudaGetSymbolAddress((void**)&Q,  g_Q);
        cudaGetSymbolAddress((void**)&K,  g_K);
        cudaGetSymbolAddress((void**)&Vt, g_Vt);
        cudaGetSymbolAddress((void**)&AO, g_AO);
    }

    const size_t SD = (size_t)SEQ * DEMB;   // 2,097,152
    const size_t SS = (size_t)SEQ * SEQ;    // 4,194,304
    float* P = out + ATTN_OFF;

    // 1) Q/K projections [4096,1024] = X @ W^T + b ; V projection -> transposed
    {
        dim3 grid(DEMB / 128, (BATCH * SEQ) / 128, 1);
        gemm_mma<128, false><<<grid, 256>>>(x1, Wq, bq, Q,
            DEMB, DEMB, DEMB, DEMB, 0,0, 0,0, 0,0, 1.f);
        gemm_mma<128, false><<<grid, 256>>>(x2, Wk, bk, K,
            DEMB, DEMB, DEMB, DEMB, 0,0, 0,0, 0,0, 1.f);
        gemm_mma<128, true ><<<grid, 256>>>(x2, Wv, bv, Vt,
            DEMB, DEMB, DEMB, DEMB, 0,0, 0,0, 0,0, 1.f);
    }

    // 2) scores = Q K^T / 8, per (b,h), into attn region of d_out
    {
        dim3 grid(SEQ / 128, SEQ / 128, BATCH * NHEAD);
        gemm_mma<128, false><<<grid, 256>>>(Q, K, nullptr, P,
            DHEAD, DEMB, DEMB, SEQ,
            SD, (size_t)DHEAD,
            SD, (size_t)DHEAD,
            (size_t)NHEAD * SS, SS,
            0.125f);
    }

    // 3) softmax rows in place
    softmax_rows<<<BATCH * NHEAD * SEQ, 256>>>(P);

    // 4) attn_out = P @ Vt^T per (b,h): M=2048, N=64, K=2048
    {
        dim3 grid(1, SEQ / 128, BATCH * NHEAD);
        gemm_mma<64, false><<<grid, 256>>>(P, Vt, nullptr, AO,
            SEQ, SEQ, SEQ, DEMB,
            (size_t)NHEAD * SS, SS,
            (size_t)(NHEAD * DHEAD) * SEQ, (size_t)DHEAD * SEQ,
            SD, (size_t)DHEAD,
            1.f);
    }

    // 5) output = AO @ Wo^T + bo
    {
        dim3 grid(DEMB / 128, (BATCH * SEQ) / 128, 1);
        gemm_mma<128, false><<<grid, 256>>>(AO, Wo, bo, out,
            DEMB, DEMB, DEMB, DEMB, 0,0, 0,0, 0,0, 1.f);
    }
}